// round 1
// baseline (speedup 1.0000x reference)
#include <cuda_runtime.h>
#include <cuda_bf16.h>
#include <math.h>

// ---------------------------------------------------------------------------
// PatchPartitioningModule: flow CNN -> deformed grid -> bilinear patch gather
// B=4, C=3, H=W=512, PATCH=64, STRIDE=32 -> N=256 patches/batch
// Output layout (float32, concatenated tuple):
//   [0, 12582912)            patches [B,256,3,64,64]
//   [12582912, 14680064)     flow    [B,2,512,512]
//   [14680064, 16777216)     deformed[B,512,512,2]
// ---------------------------------------------------------------------------

#define BB 4
#define HH 512
#define WW 512

static const size_t PATCHES_ELEMS = (size_t)BB * 256 * 3 * 64 * 64;   // 12582912
static const size_t FLOW_ELEMS    = (size_t)BB * 2 * HH * WW;         // 2097152
static const size_t FLOW_OFF      = PATCHES_ELEMS;
static const size_t DEF_OFF       = PATCHES_ELEMS + FLOW_ELEMS;

// Ping-pong activation scratch: max live tensor = [4,32,512,512] = 33554432 floats
__device__ float g_bufA[33554432];
__device__ float g_bufB[33554432];

// ---------------------------------------------------------------------------
// Direct 3x3 conv, padding 1, stride 1.
// Block = 256 threads = 16x16 output tile. grid.z = B * (COUT/CHUNK).
// Per-cin: cooperative load of 18x18 input tile + [9][CHUNK] weights to smem,
// then each thread does 9*CHUNK FMAs with CHUNK accumulators.
// ACT: 0 = relu, 1 = tanh
// ---------------------------------------------------------------------------
template<int CIN, int COUT, int CHUNK, int ACT>
__global__ __launch_bounds__(256)
void conv3x3_k(const float* __restrict__ in, const float* __restrict__ wt,
               const float* __restrict__ bias, float* __restrict__ out,
               int H, int W)
{
    constexpr int NCH = COUT / CHUNK;
    __shared__ float s_in[18][18];
    __shared__ float s_w[9][CHUNK];

    const int tid = threadIdx.x;
    const int tx = tid & 15;
    const int ty = tid >> 4;
    const int x0 = blockIdx.x * 16;
    const int y0 = blockIdx.y * 16;
    const int b  = blockIdx.z / NCH;
    const int ch = blockIdx.z % NCH;
    const int x = x0 + tx;
    const int y = y0 + ty;

    float acc[CHUNK];
#pragma unroll
    for (int co = 0; co < CHUNK; co++) acc[co] = 0.0f;

    for (int ci = 0; ci < CIN; ci++) {
        __syncthreads();
        // weights for this cin: w[co_g][ci][t] -> s_w[t][co]
        for (int i = tid; i < 9 * CHUNK; i += 256) {
            int t  = i / CHUNK;
            int co = i - t * CHUNK;
            int co_g = ch * CHUNK + co;
            s_w[t][co] = wt[(co_g * CIN + ci) * 9 + t];
        }
        // 18x18 input tile with zero padding
        const float* inp = in + (size_t)(b * CIN + ci) * H * W;
        for (int i = tid; i < 18 * 18; i += 256) {
            int iy = i / 18;
            int ix = i - iy * 18;
            int gy = y0 + iy - 1;
            int gx = x0 + ix - 1;
            float v = 0.0f;
            if (gy >= 0 && gy < H && gx >= 0 && gx < W) v = inp[gy * W + gx];
            s_in[iy][ix] = v;
        }
        __syncthreads();

        float iv[9];
#pragma unroll
        for (int dy = 0; dy < 3; dy++)
#pragma unroll
            for (int dx = 0; dx < 3; dx++)
                iv[dy * 3 + dx] = s_in[ty + dy][tx + dx];

#pragma unroll
        for (int t = 0; t < 9; t++) {
            float v = iv[t];
#pragma unroll
            for (int co = 0; co < CHUNK; co++)
                acc[co] = fmaf(v, s_w[t][co], acc[co]);
        }
    }

    if (x < W && y < H) {
#pragma unroll
        for (int co = 0; co < CHUNK; co++) {
            int co_g = ch * CHUNK + co;
            float r = acc[co] + bias[co_g];
            if (ACT == 0) r = fmaxf(r, 0.0f);
            else          r = tanhf(r);
            out[((size_t)(b * COUT + co_g) * H + y) * W + x] = r;
        }
    }
}

// ---------------------------------------------------------------------------
// MaxPool2d(2): in [B,C,Hin,Win] -> out [B,C,Hin/2,Win/2]
// ---------------------------------------------------------------------------
__global__ void pool2_k(const float* __restrict__ in, float* __restrict__ out,
                        int C, int Hin, int Win)
{
    int Ho = Hin >> 1, Wo = Win >> 1;
    size_t total = (size_t)BB * C * Ho * Wo;
    size_t idx = (size_t)blockIdx.x * blockDim.x + threadIdx.x;
    if (idx >= total) return;
    int x  = idx % Wo;
    size_t t = idx / Wo;
    int y  = t % Ho;
    size_t bc = t / Ho;
    const float* p = in + bc * Hin * Win + (size_t)(2 * y) * Win + 2 * x;
    float v = fmaxf(fmaxf(p[0], p[1]), fmaxf(p[Win], p[Win + 1]));
    out[idx] = v;
}

// ---------------------------------------------------------------------------
// Bilinear upsample x2, half-pixel centers, index clamp (== jax.image.resize)
// in [B,C,Hin,Win] -> out [B,C,2Hin,2Win]
// ---------------------------------------------------------------------------
__global__ void up2_k(const float* __restrict__ in, float* __restrict__ out,
                      int C, int Hin, int Win)
{
    int Ho = Hin << 1, Wo = Win << 1;
    size_t total = (size_t)BB * C * Ho * Wo;
    size_t idx = (size_t)blockIdx.x * blockDim.x + threadIdx.x;
    if (idx >= total) return;
    int x  = idx % Wo;
    size_t t = idx / Wo;
    int y  = t % Ho;
    size_t bc = t / Ho;

    float sx = (x + 0.5f) * 0.5f - 0.5f;
    float sy = (y + 0.5f) * 0.5f - 0.5f;
    int x0 = (int)floorf(sx);
    int y0 = (int)floorf(sy);
    float fx = sx - (float)x0;
    float fy = sy - (float)y0;
    int x0c = max(x0, 0), x1c = min(x0 + 1, Win - 1);
    int y0c = max(y0, 0), y1c = min(y0 + 1, Hin - 1);

    const float* p = in + bc * Hin * Win;
    float v00 = p[(size_t)y0c * Win + x0c];
    float v01 = p[(size_t)y0c * Win + x1c];
    float v10 = p[(size_t)y1c * Win + x0c];
    float v11 = p[(size_t)y1c * Win + x1c];
    out[idx] = (1.0f - fy) * ((1.0f - fx) * v00 + fx * v01)
             +          fy * ((1.0f - fx) * v10 + fx * v11);
}

// ---------------------------------------------------------------------------
// deformed[b,y,x,k] = base grid + flow * temp
// flow [B,2,512,512], deformed [B,512,512,2]
// ---------------------------------------------------------------------------
__global__ void deformed_k(const float* __restrict__ flow,
                           const float* __restrict__ temp,
                           float* __restrict__ def)
{
    size_t total = (size_t)BB * HH * WW;
    size_t idx = (size_t)blockIdx.x * blockDim.x + threadIdx.x;
    if (idx >= total) return;
    int x  = idx % WW;
    size_t t = idx / WW;
    int y  = t % HH;
    int b  = t / HH;

    float tp = temp[0];
    float gx = -1.0f + 2.0f * (float)x / (float)(WW - 1);
    float gy = -1.0f + 2.0f * (float)y / (float)(HH - 1);
    float f0 = flow[((size_t)(b * 2 + 0) * HH + y) * WW + x];
    float f1 = flow[((size_t)(b * 2 + 1) * HH + y) * WW + x];
    def[idx * 2 + 0] = gx + f0 * tp;
    def[idx * 2 + 1] = gy + f1 * tp;
}

// ---------------------------------------------------------------------------
// Patch extraction: 256 patches/batch, 64x64, 3 channels, bilinear + zeros pad.
// grid = (256, B), block = 256 threads, each thread does 16 pixels.
// ---------------------------------------------------------------------------
__global__ __launch_bounds__(256)
void patch_k(const float* __restrict__ x, const float* __restrict__ def,
             float* __restrict__ patches)
{
    const int n = blockIdx.x;
    const int b = blockIdx.y;
    const int yi = n >> 4;
    const int xi = n & 15;
    const int row = yi * 32;
    const int col = xi * 32;

    const float cx = def[((size_t)(b * HH + row) * WW + col) * 2 + 0];
    const float cy = def[((size_t)(b * HH + row) * WW + col) * 2 + 1];
    const float* img = x + (size_t)b * 3 * HH * WW;

    for (int idx = threadIdx.x; idx < 64 * 64; idx += 256) {
        int p = idx >> 6;
        int q = idx & 63;
        float pgx = cx + (-1.0f + 2.0f * (float)q / 63.0f) * 0.125f;  // PATCH/W
        float pgy = cy + (-1.0f + 2.0f * (float)p / 63.0f) * 0.125f;
        float ix = ((pgx + 1.0f) * (float)WW - 1.0f) * 0.5f;
        float iy = ((pgy + 1.0f) * (float)HH - 1.0f) * 0.5f;
        float x0f = floorf(ix);
        float y0f = floorf(iy);
        float wx = ix - x0f;
        float wy = iy - y0f;

        float a0 = 0.0f, a1 = 0.0f, a2 = 0.0f;
#pragma unroll
        for (int dy = 0; dy < 2; dy++) {
#pragma unroll
            for (int dx = 0; dx < 2; dx++) {
                float xf = x0f + (float)dx;
                float yf = y0f + (float)dy;
                float wgt = (dx ? wx : 1.0f - wx) * (dy ? wy : 1.0f - wy);
                bool valid = (xf >= 0.0f) && (xf <= (float)(WW - 1)) &&
                             (yf >= 0.0f) && (yf <= (float)(HH - 1));
                if (!valid) wgt = 0.0f;
                int xc = min(max((int)xf, 0), WW - 1);
                int yc = min(max((int)yf, 0), HH - 1);
                size_t o = (size_t)yc * WW + xc;
                a0 = fmaf(wgt, img[o], a0);
                a1 = fmaf(wgt, img[(size_t)HH * WW + o], a1);
                a2 = fmaf(wgt, img[2 * (size_t)HH * WW + o], a2);
            }
        }
        size_t ob = ((size_t)(b * 256 + n) * 3) * 4096 + idx;
        patches[ob]            = a0;
        patches[ob + 4096]     = a1;
        patches[ob + 2 * 4096] = a2;
    }
}

// ---------------------------------------------------------------------------
static inline dim3 grid1d(size_t n, int blk) {
    return dim3((unsigned)((n + blk - 1) / blk));
}

extern "C" void kernel_launch(void* const* d_in, const int* in_sizes, int n_in,
                              void* d_out, int out_size)
{
    const float* x = (const float*)d_in[0];
    const float* w[8];
    const float* bs[8];
    for (int i = 0; i < 8; i++) {
        w[i]  = (const float*)d_in[1 + 2 * i];
        bs[i] = (const float*)d_in[2 + 2 * i];
    }
    const float* temp = (const float*)d_in[17];
    float* out = (float*)d_out;

    float *A, *Bb;
    cudaGetSymbolAddress((void**)&A,  g_bufA);
    cudaGetSymbolAddress((void**)&Bb, g_bufB);

    dim3 blk(256);
    dim3 g512(32, 32, BB);       // 512x512, 1 chunk of 32
    dim3 g512_2(32, 32, BB);     // COUT=2 -> CHUNK=2 -> 1 chunk
    dim3 g256c2(16, 16, BB * 2); // 256x256, COUT=64 -> 2 chunks of 32
    dim3 g256c1(16, 16, BB);     // 256x256, COUT=32 -> 1 chunk

    // flow net
    conv3x3_k<3, 32, 32, 0><<<g512, blk>>>(x,  w[0], bs[0], A,  512, 512);
    conv3x3_k<32, 32, 32, 0><<<g512, blk>>>(A,  w[1], bs[1], Bb, 512, 512);
    pool2_k<<<grid1d((size_t)BB * 32 * 256 * 256, 256), blk>>>(Bb, A, 32, 512, 512);
    conv3x3_k<32, 64, 32, 0><<<g256c2, blk>>>(A,  w[2], bs[2], Bb, 256, 256);
    conv3x3_k<64, 64, 32, 0><<<g256c2, blk>>>(Bb, w[3], bs[3], A,  256, 256);
    pool2_k<<<grid1d((size_t)BB * 64 * 128 * 128, 256), blk>>>(A, Bb, 64, 256, 256);
    up2_k<<<grid1d((size_t)BB * 64 * 256 * 256, 256), blk>>>(Bb, A, 64, 128, 128);
    conv3x3_k<64, 64, 32, 0><<<g256c2, blk>>>(A,  w[4], bs[4], Bb, 256, 256);
    conv3x3_k<64, 32, 32, 0><<<g256c1, blk>>>(Bb, w[5], bs[5], A,  256, 256);
    up2_k<<<grid1d((size_t)BB * 32 * 512 * 512, 256), blk>>>(A, Bb, 32, 256, 256);
    conv3x3_k<32, 32, 32, 0><<<g512, blk>>>(Bb, w[6], bs[6], A, 512, 512);
    // final conv + tanh writes flow straight into d_out
    conv3x3_k<32, 2, 2, 1><<<g512_2, blk>>>(A, w[7], bs[7], out + FLOW_OFF, 512, 512);

    // deformed grid
    deformed_k<<<grid1d((size_t)BB * HH * WW, 256), blk>>>(out + FLOW_OFF, temp, out + DEF_OFF);

    // patches
    patch_k<<<dim3(256, BB), blk>>>(x, out + DEF_OFF, out);
}